// round 11
// baseline (speedup 1.0000x reference)
#include <cuda_runtime.h>
#include <cuda_fp16.h>
#include <cstdint>

#define BB 16
#define CC 64
#define NN 2048
#define TQ 64      // queries per CTA
#define TM 128     // candidates per tile
#define RS 144     // fp16 tile row stride in BYTES (128 data + 16 pad)
#define SROW 129   // fp32 score-tile row stride (words)
#define PD 12      // per-thread approx list depth (pool = 4*12 = 48)

// smem byte offsets (knn)
#define QH  0                  // 64*144 = 9216
#define MB0 9216               // 128*144 = 18432
#define MB1 27648
#define XX0 46080
#define XX1 46592
#define SOF 47104              // S[64][129] fp32 = 33024
#define SM_TOTAL 80128

// ---------------- scratch (no allocation allowed) ----------------
__device__ __half g_h[BB * NN * CC];     // fp16 [b][n][c], 128B rows
__device__ float  g_xt[BB * NN * CC];    // fp32 [b][n][c] transposed copy
__device__ float  g_xx[BB * NN];
__device__ int    g_cand[BB * NN * 48];  // 48-candidate pool per query
__device__ int    g_idx[BB * NN * 8];

__device__ __forceinline__ uint32_t smem_u32(const void* p) {
    uint32_t a;
    asm("{ .reg .u64 t; cvta.to.shared.u64 t, %1; cvt.u32.u64 %0, t; }" : "=r"(a) : "l"(p));
    return a;
}
__device__ __forceinline__ void ldsm4(uint32_t& r0, uint32_t& r1, uint32_t& r2, uint32_t& r3,
                                      uint32_t addr) {
    asm volatile("ldmatrix.sync.aligned.m8n8.x4.shared.b16 {%0,%1,%2,%3}, [%4];"
                 : "=r"(r0), "=r"(r1), "=r"(r2), "=r"(r3) : "r"(addr));
}
__device__ __forceinline__ void mma16816(float* c, const uint32_t* a, uint32_t b0, uint32_t b1) {
    asm volatile(
        "mma.sync.aligned.m16n8k16.row.col.f32.f16.f16.f32 "
        "{%0,%1,%2,%3}, {%4,%5,%6,%7}, {%8,%9}, {%0,%1,%2,%3};"
        : "+f"(c[0]), "+f"(c[1]), "+f"(c[2]), "+f"(c[3])
        : "r"(a[0]), "r"(a[1]), "r"(a[2]), "r"(a[3]), "r"(b0), "r"(b1));
}
__device__ __forceinline__ void cp16(uint32_t dst, const void* src) {
    asm volatile("cp.async.cg.shared.global [%0], [%1], 16;" :: "r"(dst), "l"(src));
}
#define CP_COMMIT() asm volatile("cp.async.commit_group;" ::: "memory")
#define CP_WAIT0()  asm volatile("cp.async.wait_group 0;" ::: "memory")

// ---------------------------------------------------------------------------
// Prep: fp16 copy + fp32 transposed copy + fp32 norms, all [b][n][c].
// ---------------------------------------------------------------------------
__global__ void prep_kernel(const float* __restrict__ x) {
    int b = blockIdx.y;
    int n = blockIdx.x * 128 + threadIdx.x;
    const float* xp = x + b * CC * NN + n;
    __half2 h2[32];
    float   xt[64];
    float s = 0.f;
#pragma unroll
    for (int c2 = 0; c2 < 32; ++c2) {
        float v0 = xp[(2 * c2) * NN];
        float v1 = xp[(2 * c2 + 1) * NN];
        s = fmaf(v0, v0, s);
        s = fmaf(v1, v1, s);
        h2[c2] = __floats2half2_rn(v0, v1);
        xt[2 * c2] = v0; xt[2 * c2 + 1] = v1;
    }
    g_xx[b * NN + n] = s;
    size_t rowo = (size_t)(b * NN + n) * CC;
    uint4* dh = (uint4*)(g_h + rowo);
    const uint4* sh = (const uint4*)h2;
#pragma unroll
    for (int i = 0; i < 8; ++i) dh[i] = sh[i];   // FIX: 64 halves = 8 uint4 (was 4)
    float4* dt = (float4*)(g_xt + rowo);
    const float4* st = (const float4*)xt;
#pragma unroll
    for (int i = 0; i < 16; ++i) dt[i] = st[i];
}

// ---------------------------------------------------------------------------
// Prefetch one fp16 M tile (128 rows) + its norms into buffer `buf`.
// ---------------------------------------------------------------------------
__device__ __forceinline__ void prefetch_tile(uint32_t sb, int buf, int b, int mb, int tid) {
    const uint4* mh = (const uint4*)(g_h + (size_t)(b * NN + mb) * CC);
    const uint32_t base = sb + (buf ? MB1 : MB0);
#pragma unroll
    for (int k = 0; k < 4; ++k) {
        int i = tid + k * 256;               // 0..1023 = 128 rows x 8 segs
        int r = i >> 3, seg = i & 7;
        cp16(base + r * RS + seg * 16, mh + r * 8 + seg);
    }
    if (tid < 32)
        cp16(sb + (buf ? XX1 : XX0) + tid * 16, g_xx + b * NN + mb + tid * 4);
    CP_COMMIT();
}

// ---------------------------------------------------------------------------
// KNN stage 1: single-pass fp16 MMA + per-thread top-12 over 32-wide quarter.
// Pool of 48 candidates per query -> g_cand.
// ---------------------------------------------------------------------------
__global__ void __launch_bounds__(256, 2) knn_kernel() {
    extern __shared__ char sm[];
    const uint32_t sb = smem_u32(sm);
    const int tid  = threadIdx.x;
    const int lane = tid & 31;
    const int w    = tid >> 5;
    const int wm   = (w & 1) * 32;
    const int wn   = (w >> 1) * 32;
    const int b    = blockIdx.y;
    const int qbase = blockIdx.x * TQ;

    // Q tile (plain stores)
    {
        const uint4* qh = (const uint4*)(g_h + (size_t)(b * NN + qbase) * CC);
        for (int i = tid; i < TQ * 8; i += 256) {
            int row = i >> 3, seg = i & 7;
            *(uint4*)(sm + QH + row * RS + seg * 16) = qh[i];
        }
    }
    prefetch_tile(sb, 0, b, 0, tid);

    float vl[PD];
    int   il[PD];
#pragma unroll
    for (int k = 0; k < PD; ++k) { vl[k] = -3.4e38f; il[k] = -1; }

    const int qown = tid & 63;
    const int qtr  = tid >> 6;

    const int lrow = lane & 15;
    const int lcol = (lane >> 4) * 16;
    const uint32_t aB = sb + QH + (wm + lrow) * RS + lcol;
    float* S = (float*)(sm + SOF);

    for (int mt = 0; mt < 16; ++mt) {
        const int cur = mt & 1;
        const uint32_t mbase = sb + (cur ? MB1 : MB0);

        CP_WAIT0();
        __syncthreads();   // cur buffer ready; prev scan done

        if (mt < 15) prefetch_tile(sb, cur ^ 1, b, (mt + 1) * TM, tid);

        float acc[2][4][4];
#pragma unroll
        for (int i = 0; i < 2; ++i)
#pragma unroll
            for (int j = 0; j < 4; ++j)
#pragma unroll
                for (int k = 0; k < 4; ++k) acc[i][j][k] = 0.f;

        const uint32_t bB = mbase + (wn + lrow) * RS + lcol;

#pragma unroll
        for (int ks = 0; ks < 4; ++ks) {
            const int ko = ks * 32;
            uint32_t aH[2][4], bH[4][2];
#pragma unroll
            for (int m2 = 0; m2 < 2; ++m2)
                ldsm4(aH[m2][0], aH[m2][1], aH[m2][2], aH[m2][3], aB + m2 * 16 * RS + ko);
#pragma unroll
            for (int np = 0; np < 2; ++np) {
                uint32_t r0, r1, r2, r3;
                ldsm4(r0, r1, r2, r3, bB + np * 16 * RS + ko);
                bH[np * 2][0] = r0; bH[np * 2][1] = r2;
                bH[np * 2 + 1][0] = r1; bH[np * 2 + 1][1] = r3;
            }
#pragma unroll
            for (int m2 = 0; m2 < 2; ++m2)
#pragma unroll
                for (int j = 0; j < 4; ++j)
                    mma16816(acc[m2][j], aH[m2], bH[j][0], bH[j][1]);
        }
        __syncthreads();   // MMA reads done

        // spill S[q][m]
        {
            const int r  = lane >> 2;
            const int cp = (lane & 3) * 2;
#pragma unroll
            for (int m2 = 0; m2 < 2; ++m2)
#pragma unroll
                for (int j = 0; j < 4; ++j) {
                    int row = wm + m2 * 16 + r;
                    int col = wn + j * 8 + cp;
                    S[row * SROW + col]           = acc[m2][j][0];
                    S[row * SROW + col + 1]       = acc[m2][j][1];
                    S[(row + 8) * SROW + col]     = acc[m2][j][2];
                    S[(row + 8) * SROW + col + 1] = acc[m2][j][3];
                }
        }
        __syncthreads();

        // scan: 4 threads per query, 32 candidates each, persistent top-12
        {
            const float* srow = &S[qown * SROW + qtr * 32];
            const float* xxp  = (const float*)(sm + (cur ? XX1 : XX0)) + qtr * 32;
            const int mofs = mt * TM + qtr * 32;
#pragma unroll 4
            for (int m = 0; m < 32; ++m) {
                float v = fmaf(2.f, srow[m], -xxp[m]);
                if (v > vl[PD - 1]) {
                    vl[PD - 1] = v;
                    il[PD - 1] = mofs + m;
#pragma unroll
                    for (int k = PD - 1; k > 0; --k) {
                        if (vl[k] > vl[k - 1]) {
                            float tv = vl[k]; vl[k] = vl[k - 1]; vl[k - 1] = tv;
                            int   ti = il[k]; il[k] = il[k - 1]; il[k - 1] = ti;
                        }
                    }
                }
            }
        }
    }

    // dump pool: 12 indices per thread, 48 per query
    {
        int* cp = &g_cand[(size_t)(b * NN + qbase + qown) * 48 + qtr * PD];
#pragma unroll
        for (int k = 0; k < PD; ++k) cp[k] = il[k];
    }
}

// ---------------------------------------------------------------------------
// Stage 2: exact fp32 rescore of the 48-candidate pool, warp per query.
// Lexicographic top-9 (val desc, idx asc) == top_k; ranks 1..8 -> g_idx.
// ---------------------------------------------------------------------------
__global__ void rescore_kernel() {
    __shared__ float qs[8][64];
    const int warp = threadIdx.x >> 5;
    const int lane = threadIdx.x & 31;
    const int q = blockIdx.x * 8 + warp;          // 0 .. BB*NN-1
    const int b = q >> 11;

    const float* qrow = g_xt + (size_t)q * 64;
    qs[warp][lane]      = qrow[lane];
    qs[warp][lane + 32] = qrow[lane + 32];
    __syncwarp();

    const int* cl = g_cand + (size_t)q * 48;
    const float* qsm = qs[warp];

    auto score = [&](int ci) -> float {
        const float4* xr = (const float4*)(g_xt + (size_t)(b * NN + ci) * 64);
        float s = 0.f;
#pragma unroll
        for (int c4 = 0; c4 < 16; ++c4) {
            float4 v = xr[c4];
            s = fmaf(v.x, qsm[c4 * 4],     s);
            s = fmaf(v.y, qsm[c4 * 4 + 1], s);
            s = fmaf(v.z, qsm[c4 * 4 + 2], s);
            s = fmaf(v.w, qsm[c4 * 4 + 3], s);
        }
        return fmaf(2.f, s, -g_xx[b * NN + ci]);
    };

    auto mkkey = [](float v, int i) -> unsigned long long {
        uint32_t f = __float_as_uint(v);
        f = (f & 0x80000000u) ? ~f : (f | 0x80000000u);
        return ((unsigned long long)f << 32) | (uint32_t)(~i);
    };

    int c0 = cl[lane];
    unsigned long long k0 = mkkey(score(c0), c0);
    unsigned long long k1 = 0;
    if (lane < 16) {
        int c1 = cl[32 + lane];
        k1 = mkkey(score(c1), c1);
    }

    int* gout = &g_idx[(size_t)q * 8];
#pragma unroll
    for (int r = 0; r < 9; ++r) {
        unsigned long long m = k0 > k1 ? k0 : k1;
#pragma unroll
        for (int o = 16; o > 0; o >>= 1) {
            unsigned long long t = __shfl_xor_sync(0xFFFFFFFFu, m, o);
            if (t > m) m = t;
        }
        if (r > 0 && lane == 0) gout[r - 1] = (int)(~(uint32_t)m);
        if (k0 == m) k0 = 0;
        if (k1 == m) k1 = 0;
    }
}

// ---------------------------------------------------------------------------
// Output assembly:
// out[b,c,n] = x[b,c,n];  out[b,c,N+n] = mean_k x[b,c,idx[b,n,k]]
// ---------------------------------------------------------------------------
__global__ void gather_kernel(const float* __restrict__ x, float* __restrict__ out) {
    __shared__ float row[NN];
    int b = blockIdx.x >> 6;
    int c = blockIdx.x & 63;
    const float* xr = x + (b * CC + c) * NN;
    for (int n = threadIdx.x; n < NN; n += blockDim.x) row[n] = xr[n];
    __syncthreads();
    const int4* gi = (const int4*)(g_idx + (size_t)b * NN * 8);
    float* o = out + (size_t)(b * CC + c) * (2 * NN);
    for (int n = threadIdx.x; n < NN; n += blockDim.x) {
        o[n] = row[n];
        int4 i0 = gi[n * 2];
        int4 i1 = gi[n * 2 + 1];
        float s = row[i0.x] + row[i0.y] + row[i0.z] + row[i0.w]
                + row[i1.x] + row[i1.y] + row[i1.z] + row[i1.w];
        o[NN + n] = s * 0.125f;
    }
}

// ---------------------------------------------------------------------------
extern "C" void kernel_launch(void* const* d_in, const int* in_sizes, int n_in,
                              void* d_out, int out_size) {
    (void)in_sizes; (void)n_in; (void)out_size;
    const float* x = (const float*)d_in[0];
    float* out = (float*)d_out;

    prep_kernel<<<dim3(16, 16), 128>>>(x);

    cudaFuncSetAttribute(knn_kernel, cudaFuncAttributeMaxDynamicSharedMemorySize, SM_TOTAL);
    knn_kernel<<<dim3(NN / TQ, BB), 256, SM_TOTAL>>>();

    rescore_kernel<<<(BB * NN) / 8, 256>>>();

    gather_kernel<<<BB * CC, 256>>>(x, out);
}